// round 11
// baseline (speedup 1.0000x reference)
#include <cuda_runtime.h>
#include <cstdint>

using u64 = unsigned long long;

// Problem constants
constexpr int NB   = 32;
constexpr int C    = 256;
constexpr int HW   = 4096;
constexpr int G    = 8;
constexpr int GS   = 32;
constexpr int NTOT = NB * HW;          // 131072
constexpr float EPSV = 1e-5f;

constexpr int PPG = 128;               // partials per group (b x hw-quarter)

// Scratch (device globals — no allocations allowed)
__device__ float g_p2[G * PPG][GS][GS];   // per-block cov partials
__device__ float g_p1[G * PPG][GS];       // per-block sum partials
__device__ float g_whi[G][GS][GS];        // whitening matrix, tf32-hi part
__device__ float g_wlo[G][GS][GS];        // tf32-lo residual
__device__ float g_beta[G][GS];           // bias - wm @ mean

// ---- misc PTX ---------------------------------------------------------------
__device__ __forceinline__ uint32_t smem_u32(const void* p) {
    uint32_t a;
    asm("{ .reg .u64 t; cvta.to.shared.u64 t, %1; cvt.u32.u64 %0, t; }"
        : "=r"(a) : "l"(p));
    return a;
}
__device__ __forceinline__ void cp16(uint32_t dst, const void* src) {
    asm volatile("cp.async.cg.shared.global [%0], [%1], 16;"
                 :: "r"(dst), "l"(src) : "memory");
}
__device__ __forceinline__ uint32_t cvt_tf32(float f) {
    uint32_t r; asm("cvt.rna.tf32.f32 %0, %1;" : "=r"(r) : "f"(f)); return r;
}
__device__ __forceinline__ void mma_tf32(float& c0, float& c1, float& c2, float& c3,
                                         uint32_t a0, uint32_t a1, uint32_t a2,
                                         uint32_t a3, uint32_t b0, uint32_t b1) {
    asm volatile(
        "mma.sync.aligned.m16n8k8.row.col.f32.tf32.tf32.f32 "
        "{%0,%1,%2,%3}, {%4,%5,%6,%7}, {%8,%9}, {%0,%1,%2,%3};"
        : "+f"(c0), "+f"(c1), "+f"(c2), "+f"(c3)
        : "r"(a0), "r"(a1), "r"(a2), "r"(a3), "r"(b0), "r"(b1));
}

constexpr int RSTRIDE = 132;           // smem row stride in floats
constexpr int TILEK   = 128;           // k per tile
constexpr uint32_t ONE_TF = 0x3F800000u;

// ---------------------------------------------------------------------------
// Kernel 1: covariance via mma.sync tf32, symmetric-tile version (R10, 29.6us).
// 1024 blocks = (g, b, hw-quarter); K=1024 per block. Only 6 of 8 output
// tiles computed; lower-left pair reconstructed by transpose in the reduce.
// launch_bounds(256,3) -> 3 CTAs/SM.
// ---------------------------------------------------------------------------
__global__ void __launch_bounds__(256, 3) k_cov(const float* __restrict__ x) {
    __shared__ __align__(16) float sbuf[2][32 * RSTRIDE];
    __shared__ float ssum[8][32];

    const int tid = threadIdx.x;
    const int wid = tid >> 5, lane = tid & 31;
    const int g1 = lane >> 2, t4 = lane & 3;

    const int bx = blockIdx.x;
    const int g = bx >> 7, b = (bx >> 2) & 31, s = bx & 3;
    const float* xb = x + (size_t)(b * C + g * GS) * HW + s * 1024;

    const uint32_t sb0 = smem_u32(&sbuf[0][0]);
    const uint32_t sb1 = smem_u32(&sbuf[1][0]);

    auto fill = [&](int t, uint32_t dstb) {
        const float* xt = xb + t * TILEK;
        #pragma unroll
        for (int j = 0; j < 4; j++) {
            int c = j * 256 + tid;
            int row = c >> 5, kq = c & 31;
            cp16(dstb + row * (RSTRIDE * 4) + kq * 16,
                 xt + (size_t)row * HW + kq * 4);
        }
        asm volatile("cp.async.commit_group;" ::: "memory");
    };

    float acc[6][4];
    float oacc[2][4];
    #pragma unroll
    for (int q = 0; q < 6; q++)
        acc[q][0] = acc[q][1] = acc[q][2] = acc[q][3] = 0.f;
    #pragma unroll
    for (int m = 0; m < 2; m++)
        oacc[m][0] = oacc[m][1] = oacc[m][2] = oacc[m][3] = 0.f;

    fill(0, sb0);
    for (int t = 0; t < 8; t++) {
        if (t + 1 < 8) {
            fill(t + 1, (t & 1) ? sb0 : sb1);
            asm volatile("cp.async.wait_group 1;" ::: "memory");
        } else {
            asm volatile("cp.async.wait_group 0;" ::: "memory");
        }
        __syncthreads();

        const float* sm = (t & 1) ? &sbuf[1][0] : &sbuf[0][0];
        #pragma unroll
        for (int kk = 0; kk < 2; kk++) {
            const int kb = wid * 16 + kk * 8;
            uint32_t af[2][4];
            #pragma unroll
            for (int m = 0; m < 2; m++) {
                const float* r0 = sm + (m * 16 + g1) * RSTRIDE + kb + t4;
                const float* r1 = sm + (m * 16 + g1 + 8) * RSTRIDE + kb + t4;
                af[m][0] = cvt_tf32(r0[0]);
                af[m][1] = cvt_tf32(r1[0]);
                af[m][2] = cvt_tf32(r0[4]);
                af[m][3] = cvt_tf32(r1[4]);
            }
            mma_tf32(acc[0][0], acc[0][1], acc[0][2], acc[0][3],
                     af[0][0], af[0][1], af[0][2], af[0][3], af[0][0], af[0][2]);
            mma_tf32(acc[1][0], acc[1][1], acc[1][2], acc[1][3],
                     af[0][0], af[0][1], af[0][2], af[0][3], af[0][1], af[0][3]);
            mma_tf32(acc[2][0], acc[2][1], acc[2][2], acc[2][3],
                     af[0][0], af[0][1], af[0][2], af[0][3], af[1][0], af[1][2]);
            mma_tf32(acc[3][0], acc[3][1], acc[3][2], acc[3][3],
                     af[0][0], af[0][1], af[0][2], af[0][3], af[1][1], af[1][3]);
            mma_tf32(acc[4][0], acc[4][1], acc[4][2], acc[4][3],
                     af[1][0], af[1][1], af[1][2], af[1][3], af[1][0], af[1][2]);
            mma_tf32(acc[5][0], acc[5][1], acc[5][2], acc[5][3],
                     af[1][0], af[1][1], af[1][2], af[1][3], af[1][1], af[1][3]);
            mma_tf32(oacc[0][0], oacc[0][1], oacc[0][2], oacc[0][3],
                     af[0][0], af[0][1], af[0][2], af[0][3], ONE_TF, ONE_TF);
            mma_tf32(oacc[1][0], oacc[1][1], oacc[1][2], oacc[1][3],
                     af[1][0], af[1][1], af[1][2], af[1][3], ONE_TF, ONE_TF);
        }
        __syncthreads();
    }

    float* sred = &sbuf[0][0];
    {
        const int tm[6] = {0, 0, 0, 0, 1, 1};
        const int tn[6] = {0, 1, 2, 3, 2, 3};
        #pragma unroll
        for (int q = 0; q < 6; q++) {
            const int r0 = tm[q] * 16 + g1, r1 = r0 + 8;
            const int cb = tn[q] * 8 + 2 * t4;
            sred[wid * 1056 + r0 * 33 + cb]     = acc[q][0];
            sred[wid * 1056 + r0 * 33 + cb + 1] = acc[q][1];
            sred[wid * 1056 + r1 * 33 + cb]     = acc[q][2];
            sred[wid * 1056 + r1 * 33 + cb + 1] = acc[q][3];
        }
        #pragma unroll
        for (int m = 0; m < 2; m++) {
            if (t4 == 0) {
                ssum[wid][m * 16 + g1]     = oacc[m][0];
                ssum[wid][m * 16 + g1 + 8] = oacc[m][2];
            }
        }
    }
    __syncthreads();

    #pragma unroll
    for (int q = 0; q < 4; q++) {
        const int idx = tid * 4 + q;
        const int r = idx >> 5, c = idx & 31;
        const bool mir = (r >= 16) & (c < 16);
        const int rr = mir ? c : r, cc = mir ? r : c;
        float v = 0.f;
        #pragma unroll
        for (int w = 0; w < 8; w++) v += sred[w * 1056 + rr * 33 + cc];
        g_p2[bx][r][c] = v;
    }
    if (tid < 32) {
        float v = 0.f;
        #pragma unroll
        for (int w = 0; w < 8; w++) v += ssum[w][tid];
        g_p1[bx][tid] = v;
    }
}

// ---------------------------------------------------------------------------
// Kernel 2: reduce partials -> sigma; sigma^{-1/2} via 6-iter Newton-Schulz
// (Gershgorin scaling). Emits tf32 hi/lo W split + folded beta.
// ---------------------------------------------------------------------------
__global__ void __launch_bounds__(1024) k_ns(const float* __restrict__ w,
                                             const float* __restrict__ bias) {
    const int g = blockIdx.x;
    const int tid = threadIdx.x;
    const int i = tid >> 5, j = tid & 31;

    __shared__ float Y[32 * 33], Z[32 * 33], T[32 * 33];
    __shared__ float red[32], sS1[32];

    float s2 = 0.f;
    #pragma unroll 16
    for (int p = 0; p < PPG; p++) s2 += g_p2[g * PPG + p][i][j];
    if (tid < 32) {
        float v = 0.f;
        #pragma unroll 16
        for (int p = 0; p < PPG; p++) v += g_p1[g * PPG + p][tid];
        sS1[tid] = v;
    }
    __syncthreads();
    const float m_i = sS1[i], m_j = sS1[j];
    float sig = s2 - m_i * m_j * (1.0f / NTOT) + (i == j ? EPSV : 0.f);

    float av = fabsf(sig);
    #pragma unroll
    for (int o = 16; o; o >>= 1) av += __shfl_xor_sync(0xFFFFFFFFu, av, o);
    if (j == 0) red[i] = av;
    __syncthreads();
    if (tid < 32) {
        float m = red[tid];
        #pragma unroll
        for (int o = 16; o; o >>= 1) m = fmaxf(m, __shfl_xor_sync(0xFFFFFFFFu, m, o));
        if (tid == 0) red[0] = m;
    }
    __syncthreads();
    const float sb = red[0];

    Y[i * 33 + j] = sig / sb;
    Z[i * 33 + j] = (i == j) ? 1.f : 0.f;
    __syncthreads();

    for (int it = 0; it < 6; it++) {
        float t = (i == j) ? 3.f : 0.f;
        #pragma unroll
        for (int k = 0; k < 32; k++) t -= Z[i * 33 + k] * Y[k * 33 + j];
        T[i * 33 + j] = t;
        __syncthreads();
        float yn = 0.f, zn = 0.f;
        #pragma unroll
        for (int k = 0; k < 32; k++) {
            yn += Y[i * 33 + k] * T[k * 33 + j];
            zn += T[i * 33 + k] * Z[k * 33 + j];
        }
        __syncthreads();
        Y[i * 33 + j] = 0.5f * yn;
        Z[i * 33 + j] = 0.5f * zn;
        __syncthreads();
    }

    const float wmv = Z[i * 33 + j] * rsqrtf(sb) * w[g * GS + i];
    const float whi = __uint_as_float(cvt_tf32(wmv));
    g_whi[g][i][j] = whi;
    g_wlo[g][i][j] = __uint_as_float(cvt_tf32(wmv - whi));

    float bv = wmv * (m_j * (1.0f / NTOT));
    #pragma unroll
    for (int o = 16; o; o >>= 1) bv += __shfl_xor_sync(0xFFFFFFFFu, bv, o);
    if (j == 0) g_beta[g][i] = bias[g * GS + i] - bv;
}

// ---------------------------------------------------------------------------
// Kernel 3: apply via mma.sync tf32, 2-term compensation (R8 geometry):
//   y = (Whi + Wlo) * tf32(x) + beta
// 512 blocks x 128 threads = (g, b, col-half); warp owns 512 cols, unroll 2.
// Streaming hints: __ldcs on x (read-once), __stcs on out (write-once).
// ---------------------------------------------------------------------------
__global__ void __launch_bounds__(128) k_apply(const float* __restrict__ x,
                                               float* __restrict__ out) {
    __shared__ float swh[GS * GS], swl[GS * GS], sbeta[GS];

    const int tid = threadIdx.x;
    const int wid = tid >> 5, lane = tid & 31;
    const int g1 = lane >> 2, t4 = lane & 3;
    const int bx = blockIdx.x;
    const int g = bx >> 6, b = (bx >> 1) & 31, s = bx & 1;

    for (int t = tid; t < GS * GS; t += 128) {
        swh[t] = ((const float*)g_whi)[g * GS * GS + t];
        swl[t] = ((const float*)g_wlo)[g * GS * GS + t];
    }
    if (tid < GS) sbeta[tid] = g_beta[g][tid];
    __syncthreads();

    uint32_t ah[2][4][4], al[2][4][4];
    #pragma unroll
    for (int m = 0; m < 2; m++)
        #pragma unroll
        for (int kt = 0; kt < 4; kt++) {
            const int r0 = (m * 16 + g1) * GS, r1 = r0 + 8 * GS;
            const int c0 = kt * 8 + t4, c1 = c0 + 4;
            ah[m][kt][0] = __float_as_uint(swh[r0 + c0]);
            ah[m][kt][1] = __float_as_uint(swh[r1 + c0]);
            ah[m][kt][2] = __float_as_uint(swh[r0 + c1]);
            ah[m][kt][3] = __float_as_uint(swh[r1 + c1]);
            al[m][kt][0] = __float_as_uint(swl[r0 + c0]);
            al[m][kt][1] = __float_as_uint(swl[r1 + c0]);
            al[m][kt][2] = __float_as_uint(swl[r0 + c1]);
            al[m][kt][3] = __float_as_uint(swl[r1 + c1]);
        }
    const float be0 = sbeta[g1], be8 = sbeta[g1 + 8];
    const float be16 = sbeta[g1 + 16], be24 = sbeta[g1 + 24];

    const size_t base = (size_t)(b * C + g * GS) * HW;
    const float* xb = x + base;
    float* ob = out + base;
    const int col0 = s * 2048 + wid * 512;

    #pragma unroll 2
    for (int it = 0; it < 64; it++) {
        const int n0 = col0 + it * 8;
        const float* xc = xb + n0 + g1;

        uint32_t bh[4][2];
        #pragma unroll
        for (int kt = 0; kt < 4; kt++) {
            bh[kt][0] = cvt_tf32(__ldcs(&xc[(size_t)(kt * 8 + t4) * HW]));
            bh[kt][1] = cvt_tf32(__ldcs(&xc[(size_t)(kt * 8 + t4 + 4) * HW]));
        }

        #pragma unroll
        for (int m = 0; m < 2; m++) {
            float c0 = (m == 0) ? be0 : be16;
            float c2 = (m == 0) ? be8 : be24;
            float c1 = c0, c3 = c2;
            #pragma unroll
            for (int kt = 0; kt < 4; kt++) {
                mma_tf32(c0, c1, c2, c3,
                         ah[m][kt][0], ah[m][kt][1], ah[m][kt][2], ah[m][kt][3],
                         bh[kt][0], bh[kt][1]);
                mma_tf32(c0, c1, c2, c3,
                         al[m][kt][0], al[m][kt][1], al[m][kt][2], al[m][kt][3],
                         bh[kt][0], bh[kt][1]);
            }
            float* o0 = ob + (size_t)(m * 16 + g1) * HW + n0 + 2 * t4;
            float* o1 = o0 + (size_t)8 * HW;
            __stcs((float2*)o0, make_float2(c0, c1));
            __stcs((float2*)o1, make_float2(c2, c3));
        }
    }
}

// ---------------------------------------------------------------------------
extern "C" void kernel_launch(void* const* d_in, const int* in_sizes, int n_in,
                              void* d_out, int out_size) {
    const float* x    = (const float*)d_in[0];
    const float* w    = (const float*)d_in[1];
    const float* bias = (const float*)d_in[2];
    float* out        = (float*)d_out;

    k_cov<<<G * NB * 4, 256>>>(x);
    k_ns<<<G, 1024>>>(w, bias);
    k_apply<<<G * NB * 2, 128>>>(x, out);
}

// round 13
// speedup vs baseline: 1.1004x; 1.1004x over previous
#include <cuda_runtime.h>
#include <cstdint>

using u64 = unsigned long long;

// Problem constants
constexpr int NB   = 32;
constexpr int C    = 256;
constexpr int HW   = 4096;
constexpr int G    = 8;
constexpr int GS   = 32;
constexpr int NTOT = NB * HW;          // 131072
constexpr float EPSV = 1e-5f;

constexpr int PPG = 128;               // partials per group (b x hw-quarter)

// Scratch (device globals — no allocations allowed)
__device__ float g_p2[G * PPG][GS][GS];   // per-block cov partials
__device__ float g_p1[G * PPG][GS];       // per-block sum partials
__device__ float g_whi[G][GS][GS];        // whitening matrix (tf32-rounded)
__device__ float g_beta[G][GS];           // bias - wm @ mean

// ---- misc PTX ---------------------------------------------------------------
__device__ __forceinline__ uint32_t smem_u32(const void* p) {
    uint32_t a;
    asm("{ .reg .u64 t; cvta.to.shared.u64 t, %1; cvt.u32.u64 %0, t; }"
        : "=r"(a) : "l"(p));
    return a;
}
__device__ __forceinline__ void cp16(uint32_t dst, const void* src) {
    asm volatile("cp.async.cg.shared.global [%0], [%1], 16;"
                 :: "r"(dst), "l"(src) : "memory");
}
__device__ __forceinline__ uint32_t cvt_tf32(float f) {
    uint32_t r; asm("cvt.rna.tf32.f32 %0, %1;" : "=r"(r) : "f"(f)); return r;
}
__device__ __forceinline__ void mma_tf32(float& c0, float& c1, float& c2, float& c3,
                                         uint32_t a0, uint32_t a1, uint32_t a2,
                                         uint32_t a3, uint32_t b0, uint32_t b1) {
    asm volatile(
        "mma.sync.aligned.m16n8k8.row.col.f32.tf32.tf32.f32 "
        "{%0,%1,%2,%3}, {%4,%5,%6,%7}, {%8,%9}, {%0,%1,%2,%3};"
        : "+f"(c0), "+f"(c1), "+f"(c2), "+f"(c3)
        : "r"(a0), "r"(a1), "r"(a2), "r"(a3), "r"(b0), "r"(b1));
}

constexpr int RSTRIDE = 132;           // smem row stride in floats
constexpr int TILEK   = 128;           // k per tile
constexpr uint32_t ONE_TF = 0x3F800000u;

// ---------------------------------------------------------------------------
// Kernel 1: covariance via mma.sync tf32, symmetric-tile version (29.6-29.9us
// measured). 1024 blocks = (g, b, hw-quarter); K=1024 per block. Only 6 of 8
// output tiles computed; lower-left reconstructed by transpose in the reduce.
// ---------------------------------------------------------------------------
__global__ void __launch_bounds__(256, 3) k_cov(const float* __restrict__ x) {
    __shared__ __align__(16) float sbuf[2][32 * RSTRIDE];
    __shared__ float ssum[8][32];

    const int tid = threadIdx.x;
    const int wid = tid >> 5, lane = tid & 31;
    const int g1 = lane >> 2, t4 = lane & 3;

    const int bx = blockIdx.x;
    const int g = bx >> 7, b = (bx >> 2) & 31, s = bx & 3;
    const float* xb = x + (size_t)(b * C + g * GS) * HW + s * 1024;

    const uint32_t sb0 = smem_u32(&sbuf[0][0]);
    const uint32_t sb1 = smem_u32(&sbuf[1][0]);

    auto fill = [&](int t, uint32_t dstb) {
        const float* xt = xb + t * TILEK;
        #pragma unroll
        for (int j = 0; j < 4; j++) {
            int c = j * 256 + tid;
            int row = c >> 5, kq = c & 31;
            cp16(dstb + row * (RSTRIDE * 4) + kq * 16,
                 xt + (size_t)row * HW + kq * 4);
        }
        asm volatile("cp.async.commit_group;" ::: "memory");
    };

    float acc[6][4];
    float oacc[2][4];
    #pragma unroll
    for (int q = 0; q < 6; q++)
        acc[q][0] = acc[q][1] = acc[q][2] = acc[q][3] = 0.f;
    #pragma unroll
    for (int m = 0; m < 2; m++)
        oacc[m][0] = oacc[m][1] = oacc[m][2] = oacc[m][3] = 0.f;

    fill(0, sb0);
    for (int t = 0; t < 8; t++) {
        if (t + 1 < 8) {
            fill(t + 1, (t & 1) ? sb0 : sb1);
            asm volatile("cp.async.wait_group 1;" ::: "memory");
        } else {
            asm volatile("cp.async.wait_group 0;" ::: "memory");
        }
        __syncthreads();

        const float* sm = (t & 1) ? &sbuf[1][0] : &sbuf[0][0];
        #pragma unroll
        for (int kk = 0; kk < 2; kk++) {
            const int kb = wid * 16 + kk * 8;
            uint32_t af[2][4];
            #pragma unroll
            for (int m = 0; m < 2; m++) {
                const float* r0 = sm + (m * 16 + g1) * RSTRIDE + kb + t4;
                const float* r1 = sm + (m * 16 + g1 + 8) * RSTRIDE + kb + t4;
                af[m][0] = cvt_tf32(r0[0]);
                af[m][1] = cvt_tf32(r1[0]);
                af[m][2] = cvt_tf32(r0[4]);
                af[m][3] = cvt_tf32(r1[4]);
            }
            mma_tf32(acc[0][0], acc[0][1], acc[0][2], acc[0][3],
                     af[0][0], af[0][1], af[0][2], af[0][3], af[0][0], af[0][2]);
            mma_tf32(acc[1][0], acc[1][1], acc[1][2], acc[1][3],
                     af[0][0], af[0][1], af[0][2], af[0][3], af[0][1], af[0][3]);
            mma_tf32(acc[2][0], acc[2][1], acc[2][2], acc[2][3],
                     af[0][0], af[0][1], af[0][2], af[0][3], af[1][0], af[1][2]);
            mma_tf32(acc[3][0], acc[3][1], acc[3][2], acc[3][3],
                     af[0][0], af[0][1], af[0][2], af[0][3], af[1][1], af[1][3]);
            mma_tf32(acc[4][0], acc[4][1], acc[4][2], acc[4][3],
                     af[1][0], af[1][1], af[1][2], af[1][3], af[1][0], af[1][2]);
            mma_tf32(acc[5][0], acc[5][1], acc[5][2], acc[5][3],
                     af[1][0], af[1][1], af[1][2], af[1][3], af[1][1], af[1][3]);
            mma_tf32(oacc[0][0], oacc[0][1], oacc[0][2], oacc[0][3],
                     af[0][0], af[0][1], af[0][2], af[0][3], ONE_TF, ONE_TF);
            mma_tf32(oacc[1][0], oacc[1][1], oacc[1][2], oacc[1][3],
                     af[1][0], af[1][1], af[1][2], af[1][3], ONE_TF, ONE_TF);
        }
        __syncthreads();
    }

    float* sred = &sbuf[0][0];
    {
        const int tm[6] = {0, 0, 0, 0, 1, 1};
        const int tn[6] = {0, 1, 2, 3, 2, 3};
        #pragma unroll
        for (int q = 0; q < 6; q++) {
            const int r0 = tm[q] * 16 + g1, r1 = r0 + 8;
            const int cb = tn[q] * 8 + 2 * t4;
            sred[wid * 1056 + r0 * 33 + cb]     = acc[q][0];
            sred[wid * 1056 + r0 * 33 + cb + 1] = acc[q][1];
            sred[wid * 1056 + r1 * 33 + cb]     = acc[q][2];
            sred[wid * 1056 + r1 * 33 + cb + 1] = acc[q][3];
        }
        #pragma unroll
        for (int m = 0; m < 2; m++) {
            if (t4 == 0) {
                ssum[wid][m * 16 + g1]     = oacc[m][0];
                ssum[wid][m * 16 + g1 + 8] = oacc[m][2];
            }
        }
    }
    __syncthreads();

    #pragma unroll
    for (int q = 0; q < 4; q++) {
        const int idx = tid * 4 + q;
        const int r = idx >> 5, c = idx & 31;
        const bool mir = (r >= 16) & (c < 16);
        const int rr = mir ? c : r, cc = mir ? r : c;
        float v = 0.f;
        #pragma unroll
        for (int w = 0; w < 8; w++) v += sred[w * 1056 + rr * 33 + cc];
        g_p2[bx][r][c] = v;
    }
    if (tid < 32) {
        float v = 0.f;
        #pragma unroll
        for (int w = 0; w < 8; w++) v += ssum[w][tid];
        g_p1[bx][tid] = v;
    }
}

// ---------------------------------------------------------------------------
// Kernel 2: reduce partials -> sigma; sigma^{-1/2} via 6-iter Newton-Schulz
// (Gershgorin scaling). Emits tf32-rounded W + folded beta.
// ---------------------------------------------------------------------------
__global__ void __launch_bounds__(1024) k_ns(const float* __restrict__ w,
                                             const float* __restrict__ bias) {
    const int g = blockIdx.x;
    const int tid = threadIdx.x;
    const int i = tid >> 5, j = tid & 31;

    __shared__ float Y[32 * 33], Z[32 * 33], T[32 * 33];
    __shared__ float red[32], sS1[32];

    float s2 = 0.f;
    #pragma unroll 16
    for (int p = 0; p < PPG; p++) s2 += g_p2[g * PPG + p][i][j];
    if (tid < 32) {
        float v = 0.f;
        #pragma unroll 16
        for (int p = 0; p < PPG; p++) v += g_p1[g * PPG + p][tid];
        sS1[tid] = v;
    }
    __syncthreads();
    const float m_i = sS1[i], m_j = sS1[j];
    float sig = s2 - m_i * m_j * (1.0f / NTOT) + (i == j ? EPSV : 0.f);

    float av = fabsf(sig);
    #pragma unroll
    for (int o = 16; o; o >>= 1) av += __shfl_xor_sync(0xFFFFFFFFu, av, o);
    if (j == 0) red[i] = av;
    __syncthreads();
    if (tid < 32) {
        float m = red[tid];
        #pragma unroll
        for (int o = 16; o; o >>= 1) m = fmaxf(m, __shfl_xor_sync(0xFFFFFFFFu, m, o));
        if (tid == 0) red[0] = m;
    }
    __syncthreads();
    const float sb = red[0];

    Y[i * 33 + j] = sig / sb;
    Z[i * 33 + j] = (i == j) ? 1.f : 0.f;
    __syncthreads();

    for (int it = 0; it < 6; it++) {
        float t = (i == j) ? 3.f : 0.f;
        #pragma unroll
        for (int k = 0; k < 32; k++) t -= Z[i * 33 + k] * Y[k * 33 + j];
        T[i * 33 + j] = t;
        __syncthreads();
        float yn = 0.f, zn = 0.f;
        #pragma unroll
        for (int k = 0; k < 32; k++) {
            yn += Y[i * 33 + k] * T[k * 33 + j];
            zn += T[i * 33 + k] * Z[k * 33 + j];
        }
        __syncthreads();
        Y[i * 33 + j] = 0.5f * yn;
        Z[i * 33 + j] = 0.5f * zn;
        __syncthreads();
    }

    const float wmv = Z[i * 33 + j] * rsqrtf(sb) * w[g * GS + i];
    g_whi[g][i][j] = __uint_as_float(cvt_tf32(wmv));

    float bv = wmv * (m_j * (1.0f / NTOT));
    #pragma unroll
    for (int o = 16; o; o >>= 1) bv += __shfl_xor_sync(0xFFFFFFFFu, bv, o);
    if (j == 0) g_beta[g][i] = bias[g * GS + i] - bv;
}

// ---------------------------------------------------------------------------
// Kernel 3: apply via mma.sync tf32, 1-term: y = tf32(W)*tf32(x) + beta.
// R8 geometry: 512 blocks x 128 threads = (g, b, col-half); warp owns 512
// cols, unroll 2, plain LDG/STG (streaming hints measured -13us, removed).
// ---------------------------------------------------------------------------
__global__ void __launch_bounds__(128) k_apply(const float* __restrict__ x,
                                               float* __restrict__ out) {
    __shared__ float swh[GS * GS], sbeta[GS];

    const int tid = threadIdx.x;
    const int wid = tid >> 5, lane = tid & 31;
    const int g1 = lane >> 2, t4 = lane & 3;
    const int bx = blockIdx.x;
    const int g = bx >> 6, b = (bx >> 1) & 31, s = bx & 1;

    for (int t = tid; t < GS * GS; t += 128)
        swh[t] = ((const float*)g_whi)[g * GS * GS + t];
    if (tid < GS) sbeta[tid] = g_beta[g][tid];
    __syncthreads();

    uint32_t ah[2][4][4];
    #pragma unroll
    for (int m = 0; m < 2; m++)
        #pragma unroll
        for (int kt = 0; kt < 4; kt++) {
            const int r0 = (m * 16 + g1) * GS, r1 = r0 + 8 * GS;
            const int c0 = kt * 8 + t4, c1 = c0 + 4;
            ah[m][kt][0] = __float_as_uint(swh[r0 + c0]);
            ah[m][kt][1] = __float_as_uint(swh[r1 + c0]);
            ah[m][kt][2] = __float_as_uint(swh[r0 + c1]);
            ah[m][kt][3] = __float_as_uint(swh[r1 + c1]);
        }
    const float be0 = sbeta[g1], be8 = sbeta[g1 + 8];
    const float be16 = sbeta[g1 + 16], be24 = sbeta[g1 + 24];

    const size_t base = (size_t)(b * C + g * GS) * HW;
    const float* xb = x + base;
    float* ob = out + base;
    const int col0 = s * 2048 + wid * 512;

    #pragma unroll 2
    for (int it = 0; it < 64; it++) {
        const int n0 = col0 + it * 8;
        const float* xc = xb + n0 + g1;

        uint32_t bh[4][2];
        #pragma unroll
        for (int kt = 0; kt < 4; kt++) {
            bh[kt][0] = cvt_tf32(xc[(size_t)(kt * 8 + t4) * HW]);
            bh[kt][1] = cvt_tf32(xc[(size_t)(kt * 8 + t4 + 4) * HW]);
        }

        #pragma unroll
        for (int m = 0; m < 2; m++) {
            float c0 = (m == 0) ? be0 : be16;
            float c2 = (m == 0) ? be8 : be24;
            float c1 = c0, c3 = c2;
            #pragma unroll
            for (int kt = 0; kt < 4; kt++) {
                mma_tf32(c0, c1, c2, c3,
                         ah[m][kt][0], ah[m][kt][1], ah[m][kt][2], ah[m][kt][3],
                         bh[kt][0], bh[kt][1]);
            }
            float* o0 = ob + (size_t)(m * 16 + g1) * HW + n0 + 2 * t4;
            float* o1 = o0 + (size_t)8 * HW;
            *(float2*)o0 = make_float2(c0, c1);
            *(float2*)o1 = make_float2(c2, c3);
        }
    }
}

// ---------------------------------------------------------------------------
extern "C" void kernel_launch(void* const* d_in, const int* in_sizes, int n_in,
                              void* d_out, int out_size) {
    const float* x    = (const float*)d_in[0];
    const float* w    = (const float*)d_in[1];
    const float* bias = (const float*)d_in[2];
    float* out        = (float*)d_out;

    k_cov<<<G * NB * 4, 256>>>(x);
    k_ns<<<G, 1024>>>(w, bias);
    k_apply<<<G * NB * 2, 128>>>(x, out);
}

// round 15
// speedup vs baseline: 1.1078x; 1.0067x over previous
#include <cuda_runtime.h>
#include <cstdint>

using u64 = unsigned long long;

// Problem constants
constexpr int NB   = 32;
constexpr int C    = 256;
constexpr int HW   = 4096;
constexpr int G    = 8;
constexpr int GS   = 32;
constexpr int NTOT = NB * HW;          // 131072
constexpr float EPSV = 1e-5f;

constexpr int PPG = 128;               // partials per group (b x hw-quarter)

// Scratch (device globals — no allocations allowed)
__device__ float g_p2[G * PPG][GS][GS];   // per-block cov partials
__device__ float g_p1[G * PPG][GS];       // per-block sum partials
__device__ float g_whi[G][GS][GS];        // whitening matrix (tf32-rounded)
__device__ float g_beta[G][GS];           // bias - wm @ mean

// ---- misc PTX ---------------------------------------------------------------
__device__ __forceinline__ uint32_t smem_u32(const void* p) {
    uint32_t a;
    asm("{ .reg .u64 t; cvta.to.shared.u64 t, %1; cvt.u32.u64 %0, t; }"
        : "=r"(a) : "l"(p));
    return a;
}
__device__ __forceinline__ void cp16(uint32_t dst, const void* src) {
    asm volatile("cp.async.cg.shared.global [%0], [%1], 16;"
                 :: "r"(dst), "l"(src) : "memory");
}
__device__ __forceinline__ uint32_t cvt_tf32(float f) {
    uint32_t r; asm("cvt.rna.tf32.f32 %0, %1;" : "=r"(r) : "f"(f)); return r;
}
__device__ __forceinline__ void mma_tf32(float& c0, float& c1, float& c2, float& c3,
                                         uint32_t a0, uint32_t a1, uint32_t a2,
                                         uint32_t a3, uint32_t b0, uint32_t b1) {
    asm volatile(
        "mma.sync.aligned.m16n8k8.row.col.f32.tf32.tf32.f32 "
        "{%0,%1,%2,%3}, {%4,%5,%6,%7}, {%8,%9}, {%0,%1,%2,%3};"
        : "+f"(c0), "+f"(c1), "+f"(c2), "+f"(c3)
        : "r"(a0), "r"(a1), "r"(a2), "r"(a3), "r"(b0), "r"(b1));
}

constexpr int RSTRIDE = 132;           // cov smem row stride (floats)
constexpr int TILEK   = 128;
constexpr uint32_t ONE_TF = 0x3F800000u;

// apply smem geometry
constexpr int RST2    = 136;           // apply row stride: banks 8*t4+g1 conflict-free
constexpr int TFLOATS = 32 * RST2;     // 4352 floats per tile buffer
constexpr int APPLY_SMEM_BYTES = (3 * TFLOATS + 1024 + 32) * 4;   // 56448 B

// ---------------------------------------------------------------------------
// Kernel 1: covariance via mma.sync tf32, symmetric-tile version (measured
// 29.6-30.5us). 1024 blocks = (g, b, hw-quarter); K=1024 per block.
// ---------------------------------------------------------------------------
__global__ void __launch_bounds__(256, 3) k_cov(const float* __restrict__ x) {
    __shared__ __align__(16) float sbuf[2][32 * RSTRIDE];
    __shared__ float ssum[8][32];

    const int tid = threadIdx.x;
    const int wid = tid >> 5, lane = tid & 31;
    const int g1 = lane >> 2, t4 = lane & 3;

    const int bx = blockIdx.x;
    const int g = bx >> 7, b = (bx >> 2) & 31, s = bx & 3;
    const float* xb = x + (size_t)(b * C + g * GS) * HW + s * 1024;

    const uint32_t sb0 = smem_u32(&sbuf[0][0]);
    const uint32_t sb1 = smem_u32(&sbuf[1][0]);

    auto fill = [&](int t, uint32_t dstb) {
        const float* xt = xb + t * TILEK;
        #pragma unroll
        for (int j = 0; j < 4; j++) {
            int c = j * 256 + tid;
            int row = c >> 5, kq = c & 31;
            cp16(dstb + row * (RSTRIDE * 4) + kq * 16,
                 xt + (size_t)row * HW + kq * 4);
        }
        asm volatile("cp.async.commit_group;" ::: "memory");
    };

    float acc[6][4];
    float oacc[2][4];
    #pragma unroll
    for (int q = 0; q < 6; q++)
        acc[q][0] = acc[q][1] = acc[q][2] = acc[q][3] = 0.f;
    #pragma unroll
    for (int m = 0; m < 2; m++)
        oacc[m][0] = oacc[m][1] = oacc[m][2] = oacc[m][3] = 0.f;

    fill(0, sb0);
    for (int t = 0; t < 8; t++) {
        if (t + 1 < 8) {
            fill(t + 1, (t & 1) ? sb0 : sb1);
            asm volatile("cp.async.wait_group 1;" ::: "memory");
        } else {
            asm volatile("cp.async.wait_group 0;" ::: "memory");
        }
        __syncthreads();

        const float* sm = (t & 1) ? &sbuf[1][0] : &sbuf[0][0];
        #pragma unroll
        for (int kk = 0; kk < 2; kk++) {
            const int kb = wid * 16 + kk * 8;
            uint32_t af[2][4];
            #pragma unroll
            for (int m = 0; m < 2; m++) {
                const float* r0 = sm + (m * 16 + g1) * RSTRIDE + kb + t4;
                const float* r1 = sm + (m * 16 + g1 + 8) * RSTRIDE + kb + t4;
                af[m][0] = cvt_tf32(r0[0]);
                af[m][1] = cvt_tf32(r1[0]);
                af[m][2] = cvt_tf32(r0[4]);
                af[m][3] = cvt_tf32(r1[4]);
            }
            mma_tf32(acc[0][0], acc[0][1], acc[0][2], acc[0][3],
                     af[0][0], af[0][1], af[0][2], af[0][3], af[0][0], af[0][2]);
            mma_tf32(acc[1][0], acc[1][1], acc[1][2], acc[1][3],
                     af[0][0], af[0][1], af[0][2], af[0][3], af[0][1], af[0][3]);
            mma_tf32(acc[2][0], acc[2][1], acc[2][2], acc[2][3],
                     af[0][0], af[0][1], af[0][2], af[0][3], af[1][0], af[1][2]);
            mma_tf32(acc[3][0], acc[3][1], acc[3][2], acc[3][3],
                     af[0][0], af[0][1], af[0][2], af[0][3], af[1][1], af[1][3]);
            mma_tf32(acc[4][0], acc[4][1], acc[4][2], acc[4][3],
                     af[1][0], af[1][1], af[1][2], af[1][3], af[1][0], af[1][2]);
            mma_tf32(acc[5][0], acc[5][1], acc[5][2], acc[5][3],
                     af[1][0], af[1][1], af[1][2], af[1][3], af[1][1], af[1][3]);
            mma_tf32(oacc[0][0], oacc[0][1], oacc[0][2], oacc[0][3],
                     af[0][0], af[0][1], af[0][2], af[0][3], ONE_TF, ONE_TF);
            mma_tf32(oacc[1][0], oacc[1][1], oacc[1][2], oacc[1][3],
                     af[1][0], af[1][1], af[1][2], af[1][3], ONE_TF, ONE_TF);
        }
        __syncthreads();
    }

    float* sred = &sbuf[0][0];
    {
        const int tm[6] = {0, 0, 0, 0, 1, 1};
        const int tn[6] = {0, 1, 2, 3, 2, 3};
        #pragma unroll
        for (int q = 0; q < 6; q++) {
            const int r0 = tm[q] * 16 + g1, r1 = r0 + 8;
            const int cb = tn[q] * 8 + 2 * t4;
            sred[wid * 1056 + r0 * 33 + cb]     = acc[q][0];
            sred[wid * 1056 + r0 * 33 + cb + 1] = acc[q][1];
            sred[wid * 1056 + r1 * 33 + cb]     = acc[q][2];
            sred[wid * 1056 + r1 * 33 + cb + 1] = acc[q][3];
        }
        #pragma unroll
        for (int m = 0; m < 2; m++) {
            if (t4 == 0) {
                ssum[wid][m * 16 + g1]     = oacc[m][0];
                ssum[wid][m * 16 + g1 + 8] = oacc[m][2];
            }
        }
    }
    __syncthreads();

    #pragma unroll
    for (int q = 0; q < 4; q++) {
        const int idx = tid * 4 + q;
        const int r = idx >> 5, c = idx & 31;
        const bool mir = (r >= 16) & (c < 16);
        const int rr = mir ? c : r, cc = mir ? r : c;
        float v = 0.f;
        #pragma unroll
        for (int w = 0; w < 8; w++) v += sred[w * 1056 + rr * 33 + cc];
        g_p2[bx][r][c] = v;
    }
    if (tid < 32) {
        float v = 0.f;
        #pragma unroll
        for (int w = 0; w < 8; w++) v += ssum[w][tid];
        g_p1[bx][tid] = v;
    }
}

// ---------------------------------------------------------------------------
// Kernel 2: reduce partials -> sigma; sigma^{-1/2} via 6-iter Newton-Schulz
// (Gershgorin scaling). Emits tf32-rounded W + folded beta.
// ---------------------------------------------------------------------------
__global__ void __launch_bounds__(1024) k_ns(const float* __restrict__ w,
                                             const float* __restrict__ bias) {
    const int g = blockIdx.x;
    const int tid = threadIdx.x;
    const int i = tid >> 5, j = tid & 31;

    __shared__ float Y[32 * 33], Z[32 * 33], T[32 * 33];
    __shared__ float red[32], sS1[32];

    float s2 = 0.f;
    #pragma unroll 16
    for (int p = 0; p < PPG; p++) s2 += g_p2[g * PPG + p][i][j];
    if (tid < 32) {
        float v = 0.f;
        #pragma unroll 16
        for (int p = 0; p < PPG; p++) v += g_p1[g * PPG + p][tid];
        sS1[tid] = v;
    }
    __syncthreads();
    const float m_i = sS1[i], m_j = sS1[j];
    float sig = s2 - m_i * m_j * (1.0f / NTOT) + (i == j ? EPSV : 0.f);

    float av = fabsf(sig);
    #pragma unroll
    for (int o = 16; o; o >>= 1) av += __shfl_xor_sync(0xFFFFFFFFu, av, o);
    if (j == 0) red[i] = av;
    __syncthreads();
    if (tid < 32) {
        float m = red[tid];
        #pragma unroll
        for (int o = 16; o; o >>= 1) m = fmaxf(m, __shfl_xor_sync(0xFFFFFFFFu, m, o));
        if (tid == 0) red[0] = m;
    }
    __syncthreads();
    const float sb = red[0];

    Y[i * 33 + j] = sig / sb;
    Z[i * 33 + j] = (i == j) ? 1.f : 0.f;
    __syncthreads();

    for (int it = 0; it < 6; it++) {
        float t = (i == j) ? 3.f : 0.f;
        #pragma unroll
        for (int k = 0; k < 32; k++) t -= Z[i * 33 + k] * Y[k * 33 + j];
        T[i * 33 + j] = t;
        __syncthreads();
        float yn = 0.f, zn = 0.f;
        #pragma unroll
        for (int k = 0; k < 32; k++) {
            yn += Y[i * 33 + k] * T[k * 33 + j];
            zn += T[i * 33 + k] * Z[k * 33 + j];
        }
        __syncthreads();
        Y[i * 33 + j] = 0.5f * yn;
        Z[i * 33 + j] = 0.5f * zn;
        __syncthreads();
    }

    const float wmv = Z[i * 33 + j] * rsqrtf(sb) * w[g * GS + i];
    g_whi[g][i][j] = __uint_as_float(cvt_tf32(wmv));

    float bv = wmv * (m_j * (1.0f / NTOT));
    #pragma unroll
    for (int o = 16; o; o >>= 1) bv += __shfl_xor_sync(0xFFFFFFFFu, bv, o);
    if (j == 0) g_beta[g][i] = bias[g * GS + i] - bv;
}

// ---------------------------------------------------------------------------
// Kernel 3: apply via mma.sync tf32, cov-style tiling.
// 1024 blocks = (g, b, col-quarter) x 256 threads. Per 32x128 subtile:
//   cp.async double-buffered fill (full 128B lines, stride 136 -> the
//   B-fragment LDS bank pattern 8*t4+g1 is conflict-free), 1-term MMA,
//   smem-staged epilogue with coalesced STG.128 full-line stores.
// ---------------------------------------------------------------------------
__global__ void __launch_bounds__(256) k_apply(const float* __restrict__ x,
                                               float* __restrict__ out) {
    extern __shared__ __align__(16) float dsm[];
    float* stage = dsm + 2 * TFLOATS;
    float* wtab  = dsm + 3 * TFLOATS;
    float* sbeta = wtab + 1024;

    const int tid = threadIdx.x;
    const int wid = tid >> 5, lane = tid & 31;
    const int g1 = lane >> 2, t4 = lane & 3;
    const int bx = blockIdx.x;
    const int g = bx >> 7, b = (bx >> 2) & 31, s = bx & 3;

    for (int t = tid; t < 1024; t += 256)
        wtab[t] = ((const float*)g_whi)[g * 1024 + t];
    if (tid < 32) sbeta[tid] = g_beta[g][tid];
    __syncthreads();

    uint32_t ah[2][4][4];
    #pragma unroll
    for (int m = 0; m < 2; m++)
        #pragma unroll
        for (int kt = 0; kt < 4; kt++) {
            const int r0 = (m * 16 + g1) * GS, r1 = r0 + 8 * GS;
            const int c0 = kt * 8 + t4, c1 = c0 + 4;
            ah[m][kt][0] = __float_as_uint(wtab[r0 + c0]);
            ah[m][kt][1] = __float_as_uint(wtab[r1 + c0]);
            ah[m][kt][2] = __float_as_uint(wtab[r0 + c1]);
            ah[m][kt][3] = __float_as_uint(wtab[r1 + c1]);
        }
    const float be0 = sbeta[g1], be8 = sbeta[g1 + 8];
    const float be16 = sbeta[g1 + 16], be24 = sbeta[g1 + 24];

    const size_t base = (size_t)(b * C + g * GS) * HW + s * 1024;
    const float* xb = x + base;
    float* ob = out + base;

    const uint32_t sb0 = smem_u32(dsm);
    const uint32_t sb1 = smem_u32(dsm + TFLOATS);

    auto fill = [&](int sub, uint32_t dstb) {
        const float* xt = xb + sub * 128;
        #pragma unroll
        for (int j = 0; j < 4; j++) {
            int c = j * 256 + tid;
            int row = c >> 5, kq = c & 31;
            cp16(dstb + row * (RST2 * 4) + kq * 16,
                 xt + (size_t)row * HW + kq * 4);
        }
        asm volatile("cp.async.commit_group;" ::: "memory");
    };

    fill(0, sb0);
    for (int sub = 0; sub < 8; sub++) {
        if (sub + 1 < 8) {
            fill(sub + 1, (sub & 1) ? sb0 : sb1);
            asm volatile("cp.async.wait_group 1;" ::: "memory");
        } else {
            asm volatile("cp.async.wait_group 0;" ::: "memory");
        }
        __syncthreads();
        const float* sm = dsm + (sub & 1) * TFLOATS;

        float cc[2][2][4];
        #pragma unroll
        for (int ch = 0; ch < 2; ch++) {
            const int n0 = wid * 16 + ch * 8;
            uint32_t bh[4][2];
            #pragma unroll
            for (int kt = 0; kt < 4; kt++) {
                bh[kt][0] = cvt_tf32(sm[(kt * 8 + t4) * RST2 + n0 + g1]);
                bh[kt][1] = cvt_tf32(sm[(kt * 8 + t4 + 4) * RST2 + n0 + g1]);
            }
            #pragma unroll
            for (int m = 0; m < 2; m++) {
                float c0 = (m == 0) ? be0 : be16;
                float c2 = (m == 0) ? be8 : be24;
                float c1 = c0, c3 = c2;
                #pragma unroll
                for (int kt = 0; kt < 4; kt++)
                    mma_tf32(c0, c1, c2, c3,
                             ah[m][kt][0], ah[m][kt][1], ah[m][kt][2], ah[m][kt][3],
                             bh[kt][0], bh[kt][1]);
                cc[ch][m][0] = c0; cc[ch][m][1] = c1;
                cc[ch][m][2] = c2; cc[ch][m][3] = c3;
            }
        }

        // stage the 32x128 result tile
        #pragma unroll
        for (int ch = 0; ch < 2; ch++)
            #pragma unroll
            for (int m = 0; m < 2; m++) {
                const int colr = wid * 16 + ch * 8 + 2 * t4;
                *(float2*)&stage[(m * 16 + g1) * RST2 + colr] =
                    make_float2(cc[ch][m][0], cc[ch][m][1]);
                *(float2*)&stage[(m * 16 + g1 + 8) * RST2 + colr] =
                    make_float2(cc[ch][m][2], cc[ch][m][3]);
            }
        __syncthreads();

        // coalesced full-line store
        const int colbase = sub * 128;
        #pragma unroll
        for (int q = 0; q < 4; q++) {
            const int idx = tid + 256 * q;
            const int row = idx >> 5, kq = idx & 31;
            float4 v = *(const float4*)&stage[row * RST2 + kq * 4];
            *(float4*)&ob[(size_t)row * HW + colbase + kq * 4] = v;
        }
        __syncthreads();
    }
}

// ---------------------------------------------------------------------------
extern "C" void kernel_launch(void* const* d_in, const int* in_sizes, int n_in,
                              void* d_out, int out_size) {
    const float* x    = (const float*)d_in[0];
    const float* w    = (const float*)d_in[1];
    const float* bias = (const float*)d_in[2];
    float* out        = (float*)d_out;

    cudaFuncSetAttribute(k_apply, cudaFuncAttributeMaxDynamicSharedMemorySize,
                         APPLY_SMEM_BYTES);
    k_cov<<<G * NB * 4, 256>>>(x);
    k_ns<<<G, 1024>>>(w, bias);
    k_apply<<<G * NB * 4, 256, APPLY_SMEM_BYTES>>>(x, out);
}

// round 17
// speedup vs baseline: 1.1698x; 1.0559x over previous
#include <cuda_runtime.h>
#include <cstdint>

using u64 = unsigned long long;

// Problem constants
constexpr int NB   = 32;
constexpr int C    = 256;
constexpr int HW   = 4096;
constexpr int G    = 8;
constexpr int GS   = 32;
constexpr int NTOT = NB * HW;          // 131072
constexpr float EPSV = 1e-5f;

constexpr int PPG = 128;               // partials per group (b x hw-quarter)
constexpr int NSL = 8;                 // reduce slices per group
constexpr int SLP = PPG / NSL;         // partials per slice = 16

// Scratch (device globals — no allocations allowed)
__device__ float g_p2[G * PPG][GS][GS];   // per-block cov partials
__device__ float g_p1[G * PPG][GS];       // per-block sum partials
__device__ float g_p2r[G * NSL][GS][GS];  // stage-1 reduced partials
__device__ float g_p1r[G * NSL][GS];
__device__ float g_whi[G][GS][GS];        // whitening matrix (tf32-rounded)
__device__ float g_beta[G][GS];           // bias - wm @ mean

// ---- misc PTX ---------------------------------------------------------------
__device__ __forceinline__ uint32_t smem_u32(const void* p) {
    uint32_t a;
    asm("{ .reg .u64 t; cvta.to.shared.u64 t, %1; cvt.u32.u64 %0, t; }"
        : "=r"(a) : "l"(p));
    return a;
}
__device__ __forceinline__ void cp16(uint32_t dst, const void* src) {
    asm volatile("cp.async.cg.shared.global [%0], [%1], 16;"
                 :: "r"(dst), "l"(src) : "memory");
}
__device__ __forceinline__ uint32_t cvt_tf32(float f) {
    uint32_t r; asm("cvt.rna.tf32.f32 %0, %1;" : "=r"(r) : "f"(f)); return r;
}
__device__ __forceinline__ void mma_tf32(float& c0, float& c1, float& c2, float& c3,
                                         uint32_t a0, uint32_t a1, uint32_t a2,
                                         uint32_t a3, uint32_t b0, uint32_t b1) {
    asm volatile(
        "mma.sync.aligned.m16n8k8.row.col.f32.tf32.tf32.f32 "
        "{%0,%1,%2,%3}, {%4,%5,%6,%7}, {%8,%9}, {%0,%1,%2,%3};"
        : "+f"(c0), "+f"(c1), "+f"(c2), "+f"(c3)
        : "r"(a0), "r"(a1), "r"(a2), "r"(a3), "r"(b0), "r"(b1));
}

constexpr int RSTRIDE = 132;           // cov smem row stride (floats)
constexpr int TILEK   = 128;
constexpr int COV_TF  = 32 * RSTRIDE;  // floats per cov tile buffer
constexpr int COV_SMEM_BYTES = 3 * COV_TF * 4;   // 50688 B (3-stage)
constexpr uint32_t ONE_TF = 0x3F800000u;

// apply smem geometry
constexpr int RST2    = 136;
constexpr int TFLOATS = 32 * RST2;
constexpr int APPLY_SMEM_BYTES = (3 * TFLOATS + 1024 + 32) * 4;   // 56448 B

// ---------------------------------------------------------------------------
// Kernel 1: covariance via mma.sync tf32, symmetric tiles, 3-stage cp.async.
// 1024 blocks = (g, b, hw-quarter); K=1024 per block.
// ---------------------------------------------------------------------------
__global__ void __launch_bounds__(256, 3) k_cov(const float* __restrict__ x) {
    extern __shared__ __align__(16) float csm[];
    __shared__ float ssum[8][32];

    const int tid = threadIdx.x;
    const int wid = tid >> 5, lane = tid & 31;
    const int g1 = lane >> 2, t4 = lane & 3;

    const int bx = blockIdx.x;
    const int g = bx >> 7, b = (bx >> 2) & 31, s = bx & 3;
    const float* xb = x + (size_t)(b * C + g * GS) * HW + s * 1024;

    uint32_t sb[3];
    #pragma unroll
    for (int q = 0; q < 3; q++) sb[q] = smem_u32(csm + q * COV_TF);

    auto fill = [&](int t, uint32_t dstb) {
        const float* xt = xb + t * TILEK;
        #pragma unroll
        for (int j = 0; j < 4; j++) {
            int c = j * 256 + tid;
            int row = c >> 5, kq = c & 31;
            cp16(dstb + row * (RSTRIDE * 4) + kq * 16,
                 xt + (size_t)row * HW + kq * 4);
        }
        asm volatile("cp.async.commit_group;" ::: "memory");
    };

    float acc[6][4];
    float oacc[2][4];
    #pragma unroll
    for (int q = 0; q < 6; q++)
        acc[q][0] = acc[q][1] = acc[q][2] = acc[q][3] = 0.f;
    #pragma unroll
    for (int m = 0; m < 2; m++)
        oacc[m][0] = oacc[m][1] = oacc[m][2] = oacc[m][3] = 0.f;

    fill(0, sb[0]);
    fill(1, sb[1]);
    for (int t = 0; t < 8; t++) {
        if (t + 2 < 8) {
            fill(t + 2, sb[(t + 2) % 3]);
            asm volatile("cp.async.wait_group 2;" ::: "memory");
        } else if (t + 1 < 8) {
            asm volatile("cp.async.wait_group 1;" ::: "memory");
        } else {
            asm volatile("cp.async.wait_group 0;" ::: "memory");
        }
        __syncthreads();

        const float* sm = csm + (t % 3) * COV_TF;
        #pragma unroll
        for (int kk = 0; kk < 2; kk++) {
            const int kb = wid * 16 + kk * 8;
            uint32_t af[2][4];
            #pragma unroll
            for (int m = 0; m < 2; m++) {
                const float* r0 = sm + (m * 16 + g1) * RSTRIDE + kb + t4;
                const float* r1 = sm + (m * 16 + g1 + 8) * RSTRIDE + kb + t4;
                af[m][0] = cvt_tf32(r0[0]);
                af[m][1] = cvt_tf32(r1[0]);
                af[m][2] = cvt_tf32(r0[4]);
                af[m][3] = cvt_tf32(r1[4]);
            }
            mma_tf32(acc[0][0], acc[0][1], acc[0][2], acc[0][3],
                     af[0][0], af[0][1], af[0][2], af[0][3], af[0][0], af[0][2]);
            mma_tf32(acc[1][0], acc[1][1], acc[1][2], acc[1][3],
                     af[0][0], af[0][1], af[0][2], af[0][3], af[0][1], af[0][3]);
            mma_tf32(acc[2][0], acc[2][1], acc[2][2], acc[2][3],
                     af[0][0], af[0][1], af[0][2], af[0][3], af[1][0], af[1][2]);
            mma_tf32(acc[3][0], acc[3][1], acc[3][2], acc[3][3],
                     af[0][0], af[0][1], af[0][2], af[0][3], af[1][1], af[1][3]);
            mma_tf32(acc[4][0], acc[4][1], acc[4][2], acc[4][3],
                     af[1][0], af[1][1], af[1][2], af[1][3], af[1][0], af[1][2]);
            mma_tf32(acc[5][0], acc[5][1], acc[5][2], acc[5][3],
                     af[1][0], af[1][1], af[1][2], af[1][3], af[1][1], af[1][3]);
            mma_tf32(oacc[0][0], oacc[0][1], oacc[0][2], oacc[0][3],
                     af[0][0], af[0][1], af[0][2], af[0][3], ONE_TF, ONE_TF);
            mma_tf32(oacc[1][0], oacc[1][1], oacc[1][2], oacc[1][3],
                     af[1][0], af[1][1], af[1][2], af[1][3], ONE_TF, ONE_TF);
        }
        __syncthreads();
    }

    float* sred = csm;     // overlay [8][32][33] on the tile buffers
    {
        const int tm[6] = {0, 0, 0, 0, 1, 1};
        const int tn[6] = {0, 1, 2, 3, 2, 3};
        #pragma unroll
        for (int q = 0; q < 6; q++) {
            const int r0 = tm[q] * 16 + g1, r1 = r0 + 8;
            const int cb = tn[q] * 8 + 2 * t4;
            sred[wid * 1056 + r0 * 33 + cb]     = acc[q][0];
            sred[wid * 1056 + r0 * 33 + cb + 1] = acc[q][1];
            sred[wid * 1056 + r1 * 33 + cb]     = acc[q][2];
            sred[wid * 1056 + r1 * 33 + cb + 1] = acc[q][3];
        }
        #pragma unroll
        for (int m = 0; m < 2; m++) {
            if (t4 == 0) {
                ssum[wid][m * 16 + g1]     = oacc[m][0];
                ssum[wid][m * 16 + g1 + 8] = oacc[m][2];
            }
        }
    }
    __syncthreads();

    #pragma unroll
    for (int q = 0; q < 4; q++) {
        const int idx = tid * 4 + q;
        const int r = idx >> 5, c = idx & 31;
        const bool mir = (r >= 16) & (c < 16);
        const int rr = mir ? c : r, cc = mir ? r : c;
        float v = 0.f;
        #pragma unroll
        for (int w = 0; w < 8; w++) v += sred[w * 1056 + rr * 33 + cc];
        g_p2[bx][r][c] = v;
    }
    if (tid < 32) {
        float v = 0.f;
        #pragma unroll
        for (int w = 0; w < 8; w++) v += ssum[w][tid];
        g_p1[bx][tid] = v;
    }
}

// ---------------------------------------------------------------------------
// Kernel 1b: wide stage-1 reduce of the partials (128 -> 8 per group).
// 64 blocks x 256 threads at full-chip parallelism.
// ---------------------------------------------------------------------------
__global__ void __launch_bounds__(256) k_red() {
    const int bx = blockIdx.x;          // g * NSL + slice
    const int tid = threadIdx.x;
    const int base = (bx >> 3) * PPG + (bx & 7) * SLP;

    #pragma unroll
    for (int q = 0; q < 4; q++) {
        const int idx = tid + 256 * q;
        const int r = idx >> 5, c = idx & 31;
        float v = 0.f;
        #pragma unroll
        for (int p = 0; p < SLP; p++) v += g_p2[base + p][r][c];
        g_p2r[bx][r][c] = v;
    }
    if (tid < 32) {
        float v = 0.f;
        #pragma unroll
        for (int p = 0; p < SLP; p++) v += g_p1[base + p][tid];
        g_p1r[bx][tid] = v;
    }
}

// ---------------------------------------------------------------------------
// Kernel 2: depth-8 reduce -> sigma; sigma^{-1/2} via 5-iter Newton-Schulz
// (Gershgorin scaling; e0<=0.3 -> e5 ~ 1e-20). Emits tf32 W + folded beta.
// ---------------------------------------------------------------------------
__global__ void __launch_bounds__(1024) k_ns(const float* __restrict__ w,
                                             const float* __restrict__ bias) {
    const int g = blockIdx.x;
    const int tid = threadIdx.x;
    const int i = tid >> 5, j = tid & 31;

    __shared__ float Y[32 * 33], Z[32 * 33], T[32 * 33];
    __shared__ float red[32], sS1[32];

    float s2 = 0.f;
    #pragma unroll
    for (int p = 0; p < NSL; p++) s2 += g_p2r[g * NSL + p][i][j];
    if (tid < 32) {
        float v = 0.f;
        #pragma unroll
        for (int p = 0; p < NSL; p++) v += g_p1r[g * NSL + p][tid];
        sS1[tid] = v;
    }
    __syncthreads();
    const float m_i = sS1[i], m_j = sS1[j];
    float sig = s2 - m_i * m_j * (1.0f / NTOT) + (i == j ? EPSV : 0.f);

    float av = fabsf(sig);
    #pragma unroll
    for (int o = 16; o; o >>= 1) av += __shfl_xor_sync(0xFFFFFFFFu, av, o);
    if (j == 0) red[i] = av;
    __syncthreads();
    if (tid < 32) {
        float m = red[tid];
        #pragma unroll
        for (int o = 16; o; o >>= 1) m = fmaxf(m, __shfl_xor_sync(0xFFFFFFFFu, m, o));
        if (tid == 0) red[0] = m;
    }
    __syncthreads();
    const float sb = red[0];

    Y[i * 33 + j] = sig / sb;
    Z[i * 33 + j] = (i == j) ? 1.f : 0.f;
    __syncthreads();

    for (int it = 0; it < 5; it++) {
        float t = (i == j) ? 3.f : 0.f;
        #pragma unroll
        for (int k = 0; k < 32; k++) t -= Z[i * 33 + k] * Y[k * 33 + j];
        T[i * 33 + j] = t;
        __syncthreads();
        float yn = 0.f, zn = 0.f;
        #pragma unroll
        for (int k = 0; k < 32; k++) {
            yn += Y[i * 33 + k] * T[k * 33 + j];
            zn += T[i * 33 + k] * Z[k * 33 + j];
        }
        __syncthreads();
        Y[i * 33 + j] = 0.5f * yn;
        Z[i * 33 + j] = 0.5f * zn;
        __syncthreads();
    }

    const float wmv = Z[i * 33 + j] * rsqrtf(sb) * w[g * GS + i];
    g_whi[g][i][j] = __uint_as_float(cvt_tf32(wmv));

    float bv = wmv * (m_j * (1.0f / NTOT));
    #pragma unroll
    for (int o = 16; o; o >>= 1) bv += __shfl_xor_sync(0xFFFFFFFFu, bv, o);
    if (j == 0) g_beta[g][i] = bias[g * GS + i] - bv;
}

// ---------------------------------------------------------------------------
// Kernel 3: apply via mma.sync tf32, cov-style tiling (R15, at memory floor).
// ---------------------------------------------------------------------------
__global__ void __launch_bounds__(256) k_apply(const float* __restrict__ x,
                                               float* __restrict__ out) {
    extern __shared__ __align__(16) float dsm[];
    float* stage = dsm + 2 * TFLOATS;
    float* wtab  = dsm + 3 * TFLOATS;
    float* sbeta = wtab + 1024;

    const int tid = threadIdx.x;
    const int wid = tid >> 5, lane = tid & 31;
    const int g1 = lane >> 2, t4 = lane & 3;
    const int bx = blockIdx.x;
    const int g = bx >> 7, b = (bx >> 2) & 31, s = bx & 3;

    for (int t = tid; t < 1024; t += 256)
        wtab[t] = ((const float*)g_whi)[g * 1024 + t];
    if (tid < 32) sbeta[tid] = g_beta[g][tid];
    __syncthreads();

    uint32_t ah[2][4][4];
    #pragma unroll
    for (int m = 0; m < 2; m++)
        #pragma unroll
        for (int kt = 0; kt < 4; kt++) {
            const int r0 = (m * 16 + g1) * GS, r1 = r0 + 8 * GS;
            const int c0 = kt * 8 + t4, c1 = c0 + 4;
            ah[m][kt][0] = __float_as_uint(wtab[r0 + c0]);
            ah[m][kt][1] = __float_as_uint(wtab[r1 + c0]);
            ah[m][kt][2] = __float_as_uint(wtab[r0 + c1]);
            ah[m][kt][3] = __float_as_uint(wtab[r1 + c1]);
        }
    const float be0 = sbeta[g1], be8 = sbeta[g1 + 8];
    const float be16 = sbeta[g1 + 16], be24 = sbeta[g1 + 24];

    const size_t base = (size_t)(b * C + g * GS) * HW + s * 1024;
    const float* xb = x + base;
    float* ob = out + base;

    const uint32_t sb0 = smem_u32(dsm);
    const uint32_t sb1 = smem_u32(dsm + TFLOATS);

    auto fill = [&](int sub, uint32_t dstb) {
        const float* xt = xb + sub * 128;
        #pragma unroll
        for (int j = 0; j < 4; j++) {
            int c = j * 256 + tid;
            int row = c >> 5, kq = c & 31;
            cp16(dstb + row * (RST2 * 4) + kq * 16,
                 xt + (size_t)row * HW + kq * 4);
        }
        asm volatile("cp.async.commit_group;" ::: "memory");
    };

    fill(0, sb0);
    for (int sub = 0; sub < 8; sub++) {
        if (sub + 1 < 8) {
            fill(sub + 1, (sub & 1) ? sb0 : sb1);
            asm volatile("cp.async.wait_group 1;" ::: "memory");
        } else {
            asm volatile("cp.async.wait_group 0;" ::: "memory");
        }
        __syncthreads();
        const float* sm = dsm + (sub & 1) * TFLOATS;

        float cc[2][2][4];
        #pragma unroll
        for (int ch = 0; ch < 2; ch++) {
            const int n0 = wid * 16 + ch * 8;
            uint32_t bh[4][2];
            #pragma unroll
            for (int kt = 0; kt < 4; kt++) {
                bh[kt][0] = cvt_tf32(sm[(kt * 8 + t4) * RST2 + n0 + g1]);
                bh[kt][1] = cvt_tf32(sm[(kt * 8 + t4 + 4) * RST2 + n0 + g1]);
            }
            #pragma unroll
            for (int m = 0; m < 2; m++) {
                float c0 = (m == 0) ? be0 : be16;
                float c2 = (m == 0) ? be8 : be24;
                float c1 = c0, c3 = c2;
                #pragma unroll
                for (int kt = 0; kt < 4; kt++)
                    mma_tf32(c0, c1, c2, c3,
                             ah[m][kt][0], ah[m][kt][1], ah[m][kt][2], ah[m][kt][3],
                             bh[kt][0], bh[kt][1]);
                cc[ch][m][0] = c0; cc[ch][m][1] = c1;
                cc[ch][m][2] = c2; cc[ch][m][3] = c3;
            }
        }

        #pragma unroll
        for (int ch = 0; ch < 2; ch++)
            #pragma unroll
            for (int m = 0; m < 2; m++) {
                const int colr = wid * 16 + ch * 8 + 2 * t4;
                *(float2*)&stage[(m * 16 + g1) * RST2 + colr] =
                    make_float2(cc[ch][m][0], cc[ch][m][1]);
                *(float2*)&stage[(m * 16 + g1 + 8) * RST2 + colr] =
                    make_float2(cc[ch][m][2], cc[ch][m][3]);
            }
        __syncthreads();

        const int colbase = sub * 128;
        #pragma unroll
        for (int q = 0; q < 4; q++) {
            const int idx = tid + 256 * q;
            const int row = idx >> 5, kq = idx & 31;
            float4 v = *(const float4*)&stage[row * RST2 + kq * 4];
            *(float4*)&ob[(size_t)row * HW + colbase + kq * 4] = v;
        }
        __syncthreads();
    }
}

// ---------------------------------------------------------------------------
extern "C" void kernel_launch(void* const* d_in, const int* in_sizes, int n_in,
                              void* d_out, int out_size) {
    const float* x    = (const float*)d_in[0];
    const float* w    = (const float*)d_in[1];
    const float* bias = (const float*)d_in[2];
    float* out        = (float*)d_out;

    cudaFuncSetAttribute(k_cov, cudaFuncAttributeMaxDynamicSharedMemorySize,
                         COV_SMEM_BYTES);
    cudaFuncSetAttribute(k_apply, cudaFuncAttributeMaxDynamicSharedMemorySize,
                         APPLY_SMEM_BYTES);
    k_cov<<<G * NB * 4, 256, COV_SMEM_BYTES>>>(x);
    k_red<<<G * NSL, 256>>>();
    k_ns<<<G, 1024>>>(w, bias);
    k_apply<<<G * NB * 4, 256, APPLY_SMEM_BYTES>>>(x, out);
}